// round 2
// baseline (speedup 1.0000x reference)
#include <cuda_runtime.h>
#include <cstdint>
#include <cstddef>

// Problem dims
#define B_   8
#define T_   4096
#define D_   1024
#define BT_  (B_ * T_)          // 32768 rows

// GEMM tiling: block 128x256, K-step 16, 8 warps of 64x64
#define BM   128
#define BN   256
#define BK   16
#define SK   20                 // shared row stride in floats (pad for conflict-free frag reads)
#define NTHREADS 256
#define SMEM_BYTES (2 * (BM + BN) * SK * 4)   // 61440 bytes (double-buffered A+B)

// scan tiling
#define TT    64                // T tile for partial-sum / ctx kernels
#define NTILE (T_ / TT)         // 64 tiles per batch

// ---------------- scratch (device globals; no allocation APIs) ----------------
__device__ __align__(256) float g_s[BT_];                  // attention logits s[b,t]
__device__ __align__(256) float g_e[BT_];                  // exp(s - m_b)
__device__ __align__(256) float g_pex[B_ * NTILE * D_];    // per-tile sums -> exclusive prefix of e*x
__device__ __align__(256) float g_pe[B_ * NTILE];          // per-tile sums -> exclusive prefix of e
__device__ __align__(256) float g_ctx[(size_t)BT_ * D_];   // ctx[b,t,d] fp32 (128 MiB)

// ---------------- small PTX helpers ----------------
__device__ __forceinline__ void cp16(void* dst_smem, const void* src_gmem) {
    uint32_t s = (uint32_t)__cvta_generic_to_shared(dst_smem);
    asm volatile("cp.async.cg.shared.global [%0], [%1], 16;\n" :: "r"(s), "l"(src_gmem));
}
__device__ __forceinline__ void cp_commit() { asm volatile("cp.async.commit_group;\n" ::: "memory"); }
template <int N>
__device__ __forceinline__ void cp_wait() { asm volatile("cp.async.wait_group %0;\n" :: "n"(N) : "memory"); }

__device__ __forceinline__ uint32_t f2tf32(float f) {
    uint32_t r;
    asm("cvt.rna.tf32.f32 %0, %1;" : "=r"(r) : "f"(f));
    return r;
}

__device__ __forceinline__ void mma_tf32(float c[4], const uint32_t a[4], const uint32_t b[2]) {
    asm volatile(
        "mma.sync.aligned.m16n8k8.row.col.f32.tf32.tf32.f32 "
        "{%0,%1,%2,%3}, {%4,%5,%6,%7}, {%8,%9}, {%0,%1,%2,%3};\n"
        : "+f"(c[0]), "+f"(c[1]), "+f"(c[2]), "+f"(c[3])
        : "r"(a[0]), "r"(a[1]), "r"(a[2]), "r"(a[3]), "r"(b[0]), "r"(b[1]));
}

// ---------------- tile loader (A rows from x or ctx||x, B rows of weight) ----------------
template <int PHASE>
__device__ __forceinline__ void load_tiles(
    float* As, float* Bs,
    const float* __restrict__ x, const float* __restrict__ W,
    int m0, int n0, int k0, int tid, int Kb)
{
    int r = tid >> 2;            // 0..63
    int c = (tid & 3) * 4;       // 0,4,8,12
    // A tile: BM rows x BK cols
#pragma unroll
    for (int i = 0; i < 2; i++) {
        int row = r + 64 * i;
        const float* src;
        if (PHASE == 1) {
            src = x + (size_t)(m0 + row) * D_ + k0 + c;
        } else {
            if (k0 < D_) src = g_ctx + (size_t)(m0 + row) * D_ + k0 + c;
            else         src = x     + (size_t)(m0 + row) * D_ + (k0 - D_) + c;
        }
        cp16(As + row * SK + c, src);
    }
    // B tile: BN rows x BK cols (weight is [n, k] row-major -> NT gemm)
#pragma unroll
    for (int i = 0; i < 4; i++) {
        int row = r + 64 * i;
        cp16(Bs + row * SK + c, W + (size_t)(n0 + row) * Kb + k0 + c);
    }
}

// ---------------- fused GEMM kernel ----------------
// PHASE 1: C = x @ W1^T ; epilogue s[t] += sum_j tanh(C+b1[j]) * w2[j]  (atomic into g_s)
// PHASE 2: C = [ctx,x] @ Wc^T ; epilogue out = tanh(C + bc)
template <int PHASE>
__global__ __launch_bounds__(NTHREADS, 1)
void gemm_kernel(const float* __restrict__ x,
                 const float* __restrict__ W,
                 const float* __restrict__ bias,
                 const float* __restrict__ w2,
                 float* __restrict__ outp)
{
    extern __shared__ float smem[];
    float* As0 = smem;                     // 2 stages * BM*SK
    float* Bs0 = smem + 2 * BM * SK;       // 2 stages * BN*SK

    const int tid  = threadIdx.x;
    const int warp = tid >> 5;
    const int lane = tid & 31;
    const int g    = lane >> 2;            // 0..7
    const int t4   = lane & 3;             // 0..3
    const int wm   = (warp >> 2) * 64;     // warp row offset (2 rows of warps)
    const int wn   = (warp & 3) * 64;      // warp col offset (4 cols of warps)
    const int m0   = blockIdx.y * BM;
    const int n0   = blockIdx.x * BN;
    const int K    = (PHASE == 1) ? D_ : 2 * D_;
    const int KT   = K / BK;

    float acc[4][8][4];
#pragma unroll
    for (int mf = 0; mf < 4; mf++)
#pragma unroll
        for (int nf = 0; nf < 8; nf++)
#pragma unroll
            for (int i = 0; i < 4; i++) acc[mf][nf][i] = 0.f;

    // prologue: stage 0 and 1
    load_tiles<PHASE>(As0, Bs0, x, W, m0, n0, 0, tid, K);
    cp_commit();
    load_tiles<PHASE>(As0 + BM * SK, Bs0 + BN * SK, x, W, m0, n0, BK, tid, K);
    cp_commit();
    cp_wait<1>();
    __syncthreads();

    for (int kt = 0; kt < KT; kt++) {
        const int st = kt & 1;
        const float* As = As0 + st * BM * SK;
        const float* Bs = Bs0 + st * BN * SK;

#pragma unroll
        for (int kk = 0; kk < BK; kk += 8) {
            uint32_t af[4][4], bf[8][2];
#pragma unroll
            for (int mf = 0; mf < 4; mf++) {
                const float* ap = As + (wm + mf * 16 + g) * SK + kk + t4;
                af[mf][0] = f2tf32(ap[0]);            // (row g    , k t  )
                af[mf][1] = f2tf32(ap[8 * SK]);       // (row g+8  , k t  )
                af[mf][2] = f2tf32(ap[4]);            // (row g    , k t+4)
                af[mf][3] = f2tf32(ap[8 * SK + 4]);   // (row g+8  , k t+4)
            }
#pragma unroll
            for (int nf = 0; nf < 8; nf++) {
                const float* bp = Bs + (wn + nf * 8 + g) * SK + kk + t4;
                bf[nf][0] = f2tf32(bp[0]);            // (k t  , col g)
                bf[nf][1] = f2tf32(bp[4]);            // (k t+4, col g)
            }
#pragma unroll
            for (int mf = 0; mf < 4; mf++)
#pragma unroll
                for (int nf = 0; nf < 8; nf++)
                    mma_tf32(acc[mf][nf], af[mf], bf[nf]);
        }

        __syncthreads();                 // everyone done reading buffer st
        if (kt + 2 < KT)
            load_tiles<PHASE>(As0 + st * BM * SK, Bs0 + st * BN * SK, x, W, m0, n0, (kt + 2) * BK, tid, K);
        cp_commit();
        cp_wait<1>();                    // buffer for kt+1 is ready
        __syncthreads();
    }

    if (PHASE == 1) {
        // s[t] += sum over this block's 256 columns of tanh(c + b1) * w2
        __syncthreads();
        float* s_sm = smem;              // reuse: 128 row partials
        if (tid < BM) s_sm[tid] = 0.f;
        __syncthreads();
#pragma unroll
        for (int mf = 0; mf < 4; mf++) {
            float lo = 0.f, hi = 0.f;
#pragma unroll
            for (int nf = 0; nf < 8; nf++) {
                int col = n0 + wn + nf * 8 + 2 * t4;
                float bb0 = __ldg(bias + col), bb1 = __ldg(bias + col + 1);
                float ww0 = __ldg(w2 + col),   ww1 = __ldg(w2 + col + 1);
                lo += tanhf(acc[mf][nf][0] + bb0) * ww0 + tanhf(acc[mf][nf][1] + bb1) * ww1;
                hi += tanhf(acc[mf][nf][2] + bb0) * ww0 + tanhf(acc[mf][nf][3] + bb1) * ww1;
            }
            lo += __shfl_xor_sync(0xffffffffu, lo, 1);
            lo += __shfl_xor_sync(0xffffffffu, lo, 2);
            hi += __shfl_xor_sync(0xffffffffu, hi, 1);
            hi += __shfl_xor_sync(0xffffffffu, hi, 2);
            if (t4 == 0) {
                atomicAdd(&s_sm[wm + mf * 16 + g], lo);
                atomicAdd(&s_sm[wm + mf * 16 + g + 8], hi);
            }
        }
        __syncthreads();
        if (tid < BM) atomicAdd(&g_s[m0 + tid], s_sm[tid]);
    } else {
        // out = tanh(c + bc)
#pragma unroll
        for (int mf = 0; mf < 4; mf++) {
            int row = m0 + wm + mf * 16 + g;
#pragma unroll
            for (int nf = 0; nf < 8; nf++) {
                int col = n0 + wn + nf * 8 + 2 * t4;
                float bb0 = __ldg(bias + col), bb1 = __ldg(bias + col + 1);
                float2 v0 = make_float2(tanhf(acc[mf][nf][0] + bb0), tanhf(acc[mf][nf][1] + bb1));
                float2 v1 = make_float2(tanhf(acc[mf][nf][2] + bb0), tanhf(acc[mf][nf][3] + bb1));
                *(float2*)(outp + (size_t)row * D_ + col)       = v0;
                *(float2*)(outp + (size_t)(row + 8) * D_ + col) = v1;
            }
        }
    }
}

// ---------------- scalar pipeline kernels ----------------
__global__ void k_init_s(const float* __restrict__ b2) {
    int i = blockIdx.x * blockDim.x + threadIdx.x;
    if (i < BT_) g_s[i] = b2[0];
}

__global__ void k_maxexp() {
    __shared__ float red[256];
    const int b = blockIdx.x;
    const float* s = g_s + b * T_;
    float m = -1e30f;
    for (int i = threadIdx.x; i < T_; i += 256) m = fmaxf(m, s[i]);
    red[threadIdx.x] = m;
    __syncthreads();
    for (int st = 128; st > 0; st >>= 1) {
        if (threadIdx.x < st) red[threadIdx.x] = fmaxf(red[threadIdx.x], red[threadIdx.x + st]);
        __syncthreads();
    }
    m = red[0];
    for (int i = threadIdx.x; i < T_; i += 256) g_e[b * T_ + i] = expf(s[i] - m);
}

__global__ void k_partial(const float* __restrict__ x) {
    __shared__ float e_sh[TT];
    const int tile = blockIdx.x, b = blockIdx.y, tid = threadIdx.x;
    const int t0 = tile * TT;
    if (tid < TT) e_sh[tid] = g_e[b * T_ + t0 + tid];
    __syncthreads();
    const int d0 = tid * 4;
    const float4* xp = (const float4*)(x + (size_t)(b * T_ + t0) * D_ + d0);
    float4 acc = make_float4(0.f, 0.f, 0.f, 0.f);
#pragma unroll 4
    for (int t = 0; t < TT; t++) {
        float4 xv = xp[t * (D_ / 4)];
        float e = e_sh[t];
        acc.x += e * xv.x; acc.y += e * xv.y; acc.z += e * xv.z; acc.w += e * xv.w;
    }
    *(float4*)(g_pex + (size_t)(b * NTILE + tile) * D_ + d0) = acc;
    if (tid == 0) {
        float se = 0.f;
        for (int t = 0; t < TT; t++) se += e_sh[t];
        g_pe[b * NTILE + tile] = se;
    }
}

__global__ void k_scan() {
    const int b = blockIdx.x, tid = threadIdx.x;
    const int d0 = tid * 4;
    float4 run = make_float4(0.f, 0.f, 0.f, 0.f);
    for (int tile = 0; tile < NTILE; tile++) {
        float4* p = (float4*)(g_pex + (size_t)(b * NTILE + tile) * D_ + d0);
        float4 v = *p;
        *p = run;                               // exclusive prefix, in place
        run.x += v.x; run.y += v.y; run.z += v.z; run.w += v.w;
    }
    if (tid == 0) {
        float r = 0.f;
        for (int tile = 0; tile < NTILE; tile++) {
            float v = g_pe[b * NTILE + tile];
            g_pe[b * NTILE + tile] = r;
            r += v;
        }
    }
}

__global__ void k_ctx(const float* __restrict__ x) {
    __shared__ float e_sh[TT], den_sh[TT];
    const int tile = blockIdx.x, b = blockIdx.y, tid = threadIdx.x;
    const int t0 = tile * TT;
    if (tid < TT) e_sh[tid] = g_e[b * T_ + t0 + tid];
    __syncthreads();
    if (tid == 0) {
        float r = g_pe[b * NTILE + tile];
        for (int t = 0; t < TT; t++) { r += e_sh[t]; den_sh[t] = r; }
    }
    __syncthreads();
    const int d0 = tid * 4;
    float4 run = *(float4*)(g_pex + (size_t)(b * NTILE + tile) * D_ + d0);
    const float4* xp = (const float4*)(x + (size_t)(b * T_ + t0) * D_ + d0);
    float4* cp = (float4*)(g_ctx + (size_t)(b * T_ + t0) * D_ + d0);
#pragma unroll 4
    for (int t = 0; t < TT; t++) {
        float4 xv = xp[t * (D_ / 4)];
        float e = e_sh[t];
        run.x += e * xv.x; run.y += e * xv.y; run.z += e * xv.z; run.w += e * xv.w;
        float inv = 1.0f / den_sh[t];
        cp[t * (D_ / 4)] = make_float4(run.x * inv, run.y * inv, run.z * inv, run.w * inv);
    }
}

// ---------------- launch ----------------
extern "C" void kernel_launch(void* const* d_in, const int* in_sizes, int n_in,
                              void* d_out, int out_size)
{
    const float* x  = (const float*)d_in[0];
    const float* W1 = (const float*)d_in[1];
    const float* b1 = (const float*)d_in[2];
    const float* w2 = (const float*)d_in[3];
    const float* b2 = (const float*)d_in[4];
    const float* Wc = (const float*)d_in[5];
    const float* bc = (const float*)d_in[6];
    float* out = (float*)d_out;

    cudaFuncSetAttribute(gemm_kernel<1>, cudaFuncAttributeMaxDynamicSharedMemorySize, SMEM_BYTES);
    cudaFuncSetAttribute(gemm_kernel<2>, cudaFuncAttributeMaxDynamicSharedMemorySize, SMEM_BYTES);

    k_init_s<<<BT_ / 256, 256>>>(b2);

    dim3 gg(D_ / BN, BT_ / BM);   // (4, 256)
    gemm_kernel<1><<<gg, NTHREADS, SMEM_BYTES>>>(x, W1, b1, w2, nullptr);

    k_maxexp<<<B_, 256>>>();

    dim3 gp(NTILE, B_);
    k_partial<<<gp, 256>>>(x);
    k_scan<<<B_, 256>>>();
    k_ctx<<<gp, 256>>>(x);

    gemm_kernel<2><<<gg, NTHREADS, SMEM_BYTES>>>(x, Wc, bc, nullptr, out);
}

// round 4
// speedup vs baseline: 1.2181x; 1.2181x over previous
#include <cuda_runtime.h>
#include <cstdint>
#include <cstddef>

// Problem dims
#define B_   8
#define T_   4096
#define D_   1024
#define BT_  (B_ * T_)          // 32768 rows
#define NBIG 3072               // W1(1024) + Wc1(1024) + Wc2(1024)

// GEMM tiling: 128x256 CTA tile, K-step 16, 8 warps of 64x64, 4-stage pipeline
#define BM   128
#define BN   256
#define BK   16
#define KT   (D_ / BK)          // 64 k-iterations
#define NS   4
#define SKF  24                 // smem row stride in floats (96B, conflict-free for float2 frags)
#define STGF ((BM + BN) * SKF)  // floats per stage = 9216
#define SMEM_BYTES (NS * STGF * 4)   // 147456

// scan tiling
#define TT    64
#define NTILE (T_ / TT)

// ---------------- scratch ----------------
__device__ __align__(256) float g_s[BT_];
__device__ __align__(256) float g_e[BT_];
__device__ __align__(256) float g_pex[B_ * NTILE * D_];
__device__ __align__(256) float g_pe[B_ * NTILE];
__device__ __align__(256) float g_y1[(size_t)BT_ * D_];          // x @ Wc1^T
__device__ __align__(256) float g_y2[(size_t)BT_ * D_];          // x @ Wc2^T
__device__ __align__(256) float g_xr[(size_t)BT_ * D_];          // x, tf32-rounded, k-permuted
__device__ __align__(256) float g_wr[(size_t)NBIG * D_];         // [W1;Wc1;Wc2], rounded, permuted

// ---------------- PTX helpers ----------------
__device__ __forceinline__ void cp16(void* dst_smem, const void* src_gmem) {
    uint32_t s = (uint32_t)__cvta_generic_to_shared(dst_smem);
    asm volatile("cp.async.cg.shared.global [%0], [%1], 16;\n" :: "r"(s), "l"(src_gmem));
}
__device__ __forceinline__ void cp_commit() { asm volatile("cp.async.commit_group;\n" ::: "memory"); }
template <int N>
__device__ __forceinline__ void cp_wait() { asm volatile("cp.async.wait_group %0;\n" :: "n"(N) : "memory"); }

__device__ __forceinline__ float rna_tf32(float f) {
    uint32_t r;
    asm("cvt.rna.tf32.f32 %0, %1;" : "=r"(r) : "f"(f));
    return __uint_as_float(r);
}

__device__ __forceinline__ void mma_tf32(float c[4], const uint32_t a[4], const uint32_t b[2]) {
    asm volatile(
        "mma.sync.aligned.m16n8k8.row.col.f32.tf32.tf32.f32 "
        "{%0,%1,%2,%3}, {%4,%5,%6,%7}, {%8,%9}, {%0,%1,%2,%3};\n"
        : "+f"(c[0]), "+f"(c[1]), "+f"(c[2]), "+f"(c[3])
        : "r"(a[0]), "r"(a[1]), "r"(a[2]), "r"(a[3]), "r"(b[0]), "r"(b[1]));
}

// ---------------- prepack kernels ----------------
// k-group permutation: [k0,k4,k1,k5,k2,k6,k3,k7] so lane t4 reads (k=t4, k=t4+4) as one float2.
__global__ void k_round_x(const float* __restrict__ x) {
    size_t gidx = (size_t)blockIdx.x * blockDim.x + threadIdx.x;   // one 8-float group each
    const float4* src = (const float4*)x + gidx * 2;
    float4 a = src[0], b = src[1];
    float4 o0 = make_float4(rna_tf32(a.x), rna_tf32(b.x), rna_tf32(a.y), rna_tf32(b.y));
    float4 o1 = make_float4(rna_tf32(a.z), rna_tf32(b.z), rna_tf32(a.w), rna_tf32(b.w));
    float4* dst = (float4*)g_xr + gidx * 2;
    dst[0] = o0; dst[1] = o1;
}

__global__ void k_pack_w(const float* __restrict__ W1, const float* __restrict__ Wc) {
    size_t gidx = (size_t)blockIdx.x * blockDim.x + threadIdx.x;   // n*128 + kgroup
    int n  = (int)(gidx >> 7);
    int kg = (int)(gidx & 127);
    const float* src;
    if (n < 1024)       src = W1 + (size_t)n * 1024;
    else if (n < 2048)  src = Wc + (size_t)(n - 1024) * 2048;            // cols 0..1023 (ctx part)
    else                src = Wc + (size_t)(n - 2048) * 2048 + 1024;     // cols 1024..2047 (x part)
    const float4* s4 = (const float4*)(src + kg * 8);
    float4 a = s4[0], b = s4[1];
    float4 o0 = make_float4(rna_tf32(a.x), rna_tf32(b.x), rna_tf32(a.y), rna_tf32(b.y));
    float4 o1 = make_float4(rna_tf32(a.z), rna_tf32(b.z), rna_tf32(a.w), rna_tf32(b.w));
    float4* dst = (float4*)(g_wr + gidx * 8);
    dst[0] = o0; dst[1] = o1;
}

// ---------------- fused GEMM ----------------
// C[32768, 3072] = g_xr @ g_wr^T  (tf32 mma.sync)
// n-tiles 0-3: s += sum tanh(c+b1)*w2 ; 4-7: y1 = c ; 8-11: y2 = c
__global__ __launch_bounds__(256, 1)
void gemm_big(const float* __restrict__ b1, const float* __restrict__ w2)
{
    extern __shared__ float smem[];

    const int tid  = threadIdx.x;
    const int warp = tid >> 5;
    const int lane = tid & 31;
    const int g    = lane >> 2;            // 0..7
    const int t4   = lane & 3;             // 0..3
    const int wm   = (warp >> 2) * 64;     // 2 warp rows
    const int wn   = (warp & 3) * 64;      // 4 warp cols
    const int m0   = blockIdx.y * BM;
    const int nt   = blockIdx.x;           // 0..11

    const float* asrc0 = g_xr + (size_t)m0 * D_;
    const float* bsrc0 = g_wr + (size_t)nt * BN * D_;

    float acc[4][8][4];
#pragma unroll
    for (int mf = 0; mf < 4; mf++)
#pragma unroll
        for (int nf = 0; nf < 8; nf++)
#pragma unroll
            for (int i = 0; i < 4; i++) acc[mf][nf][i] = 0.f;

    // loader: thread -> A rows r,r+64 and B rows r..r+192, 16B chunk c
    const int lr = tid >> 2;
    const int lc = (tid & 3) * 4;

    // prologue: stages 0..NS-2
#pragma unroll
    for (int s = 0; s < NS - 1; s++) {
        float* As = smem + s * STGF;
        float* Bs = As + BM * SKF;
        const int k0 = s * BK;
#pragma unroll
        for (int i = 0; i < 2; i++) {
            int row = lr + 64 * i;
            cp16(As + row * SKF + lc, asrc0 + (size_t)row * D_ + k0 + lc);
        }
#pragma unroll
        for (int i = 0; i < 4; i++) {
            int row = lr + 64 * i;
            cp16(Bs + row * SKF + lc, bsrc0 + (size_t)row * D_ + k0 + lc);
        }
        cp_commit();
    }

    for (int kt = 0; kt < KT; kt++) {
        cp_wait<NS - 2>();
        __syncthreads();

        const float* As = smem + (kt % NS) * STGF;
        const float* Bs = As + BM * SKF;

#pragma unroll
        for (int kk = 0; kk < BK; kk += 8) {
            uint32_t af[4][4], bf[8][2];
#pragma unroll
            for (int mf = 0; mf < 4; mf++) {
                const float2 v0 = *(const float2*)(As + (wm + mf * 16 + g) * SKF + kk + 2 * t4);
                const float2 v1 = *(const float2*)(As + (wm + mf * 16 + g + 8) * SKF + kk + 2 * t4);
                af[mf][0] = __float_as_uint(v0.x);   // (row g,   k t4)
                af[mf][1] = __float_as_uint(v1.x);   // (row g+8, k t4)
                af[mf][2] = __float_as_uint(v0.y);   // (row g,   k t4+4)
                af[mf][3] = __float_as_uint(v1.y);   // (row g+8, k t4+4)
            }
#pragma unroll
            for (int nf = 0; nf < 8; nf++) {
                const float2 v = *(const float2*)(Bs + (wn + nf * 8 + g) * SKF + kk + 2 * t4);
                bf[nf][0] = __float_as_uint(v.x);    // (k t4,   col g)
                bf[nf][1] = __float_as_uint(v.y);    // (k t4+4, col g)
            }
#pragma unroll
            for (int mf = 0; mf < 4; mf++)
#pragma unroll
                for (int nf = 0; nf < 8; nf++)
                    mma_tf32(acc[mf][nf], af[mf], bf[nf]);
        }

        // refill stage computed last iteration (safe: behind this iter's barrier)
        const int kn = kt + NS - 1;
        if (kn < KT) {
            float* Asw = smem + (kn % NS) * STGF;
            float* Bsw = Asw + BM * SKF;
            const int k0 = kn * BK;
#pragma unroll
            for (int i = 0; i < 2; i++) {
                int row = lr + 64 * i;
                cp16(Asw + row * SKF + lc, asrc0 + (size_t)row * D_ + k0 + lc);
            }
#pragma unroll
            for (int i = 0; i < 4; i++) {
                int row = lr + 64 * i;
                cp16(Bsw + row * SKF + lc, bsrc0 + (size_t)row * D_ + k0 + lc);
            }
        }
        cp_commit();
    }

    // ---------------- epilogue ----------------
    if (nt < 4) {
        // s[t] += sum over this block's 256 columns of tanh(c + b1) * w2
        __syncthreads();
        float* s_sm = smem;
        if (tid < BM) s_sm[tid] = 0.f;
        __syncthreads();
#pragma unroll
        for (int mf = 0; mf < 4; mf++) {
            float lo = 0.f, hi = 0.f;
#pragma unroll
            for (int nf = 0; nf < 8; nf++) {
                int col = nt * 256 + wn + nf * 8 + 2 * t4;
                float bb0 = __ldg(b1 + col), bb1 = __ldg(b1 + col + 1);
                float ww0 = __ldg(w2 + col), ww1 = __ldg(w2 + col + 1);
                lo += tanhf(acc[mf][nf][0] + bb0) * ww0 + tanhf(acc[mf][nf][1] + bb1) * ww1;
                hi += tanhf(acc[mf][nf][2] + bb0) * ww0 + tanhf(acc[mf][nf][3] + bb1) * ww1;
            }
            lo += __shfl_xor_sync(0xffffffffu, lo, 1);
            lo += __shfl_xor_sync(0xffffffffu, lo, 2);
            hi += __shfl_xor_sync(0xffffffffu, hi, 1);
            hi += __shfl_xor_sync(0xffffffffu, hi, 2);
            if (t4 == 0) {
                atomicAdd(&s_sm[wm + mf * 16 + g], lo);
                atomicAdd(&s_sm[wm + mf * 16 + g + 8], hi);
            }
        }
        __syncthreads();
        if (tid < BM) atomicAdd(&g_s[m0 + tid], s_sm[tid]);
    } else {
        float* y = (nt < 8) ? g_y1 : g_y2;
        const int c0 = (nt - ((nt < 8) ? 4 : 8)) * 256;
#pragma unroll
        for (int mf = 0; mf < 4; mf++) {
            int row = m0 + wm + mf * 16 + g;
#pragma unroll
            for (int nf = 0; nf < 8; nf++) {
                int col = c0 + wn + nf * 8 + 2 * t4;
                *(float2*)(y + (size_t)row * D_ + col)       = make_float2(acc[mf][nf][0], acc[mf][nf][1]);
                *(float2*)(y + (size_t)(row + 8) * D_ + col) = make_float2(acc[mf][nf][2], acc[mf][nf][3]);
            }
        }
    }
}

// ---------------- scalar pipeline ----------------
__global__ void k_init_s(const float* __restrict__ b2) {
    int i = blockIdx.x * blockDim.x + threadIdx.x;
    if (i < BT_) g_s[i] = b2[0];
}

__global__ void k_maxexp() {
    __shared__ float red[256];
    const int b = blockIdx.x;
    const float* s = g_s + b * T_;
    float m = -1e30f;
    for (int i = threadIdx.x; i < T_; i += 256) m = fmaxf(m, s[i]);
    red[threadIdx.x] = m;
    __syncthreads();
    for (int st = 128; st > 0; st >>= 1) {
        if (threadIdx.x < st) red[threadIdx.x] = fmaxf(red[threadIdx.x], red[threadIdx.x + st]);
        __syncthreads();
    }
    m = red[0];
    for (int i = threadIdx.x; i < T_; i += 256) g_e[b * T_ + i] = expf(s[i] - m);
}

__global__ void k_partial() {
    __shared__ float e_sh[TT];
    const int tile = blockIdx.x, b = blockIdx.y, tid = threadIdx.x;
    const int t0 = tile * TT;
    if (tid < TT) e_sh[tid] = g_e[b * T_ + t0 + tid];
    __syncthreads();
    const int d0 = tid * 4;
    const float4* yp = (const float4*)(g_y1 + (size_t)(b * T_ + t0) * D_ + d0);
    float4 acc = make_float4(0.f, 0.f, 0.f, 0.f);
#pragma unroll 4
    for (int t = 0; t < TT; t++) {
        float4 yv = yp[t * (D_ / 4)];
        float e = e_sh[t];
        acc.x += e * yv.x; acc.y += e * yv.y; acc.z += e * yv.z; acc.w += e * yv.w;
    }
    *(float4*)(g_pex + (size_t)(b * NTILE + tile) * D_ + d0) = acc;
    if (tid == 0) {
        float se = 0.f;
        for (int t = 0; t < TT; t++) se += e_sh[t];
        g_pe[b * NTILE + tile] = se;
    }
}

__global__ void k_scan() {
    const int b = blockIdx.x, tid = threadIdx.x;
    const int d0 = tid * 4;
    float4 run = make_float4(0.f, 0.f, 0.f, 0.f);
    for (int tile = 0; tile < NTILE; tile++) {
        float4* p = (float4*)(g_pex + (size_t)(b * NTILE + tile) * D_ + d0);
        float4 v = *p;
        *p = run;
        run.x += v.x; run.y += v.y; run.z += v.z; run.w += v.w;
    }
    if (tid == 0) {
        float r = 0.f;
        for (int tile = 0; tile < NTILE; tile++) {
            float v = g_pe[b * NTILE + tile];
            g_pe[b * NTILE + tile] = r;
            r += v;
        }
    }
}

__global__ void k_final(const float* __restrict__ bc, float* __restrict__ out) {
    __shared__ float e_sh[TT], den_sh[TT];
    const int tile = blockIdx.x, b = blockIdx.y, tid = threadIdx.x;
    const int t0 = tile * TT;
    if (tid < TT) e_sh[tid] = g_e[b * T_ + t0 + tid];
    __syncthreads();
    if (tid == 0) {
        float r = g_pe[b * NTILE + tile];
        for (int t = 0; t < TT; t++) { r += e_sh[t]; den_sh[t] = r; }
    }
    __syncthreads();
    const int d0 = tid * 4;
    float4 run = *(float4*)(g_pex + (size_t)(b * NTILE + tile) * D_ + d0);
    float4 bcv = *(const float4*)(bc + d0);
    const float4* y1p = (const float4*)(g_y1 + (size_t)(b * T_ + t0) * D_ + d0);
    const float4* y2p = (const float4*)(g_y2 + (size_t)(b * T_ + t0) * D_ + d0);
    float4* op = (float4*)(out + (size_t)(b * T_ + t0) * D_ + d0);
#pragma unroll 4
    for (int t = 0; t < TT; t++) {
        float4 y1v = y1p[t * (D_ / 4)];
        float4 y2v = y2p[t * (D_ / 4)];
        float e = e_sh[t];
        run.x += e * y1v.x; run.y += e * y1v.y; run.z += e * y1v.z; run.w += e * y1v.w;
        float inv = 1.0f / den_sh[t];
        float4 o;
        o.x = tanhf(run.x * inv + y2v.x + bcv.x);
        o.y = tanhf(run.y * inv + y2v.y + bcv.y);
        o.z = tanhf(run.z * inv + y2v.z + bcv.z);
        o.w = tanhf(run.w * inv + y2v.w + bcv.w);
        op[t * (D_ / 4)] = o;
    }
}

// ---------------- launch ----------------
extern "C" void kernel_launch(void* const* d_in, const int* in_sizes, int n_in,
                              void* d_out, int out_size)
{
    const float* x  = (const float*)d_in[0];
    const float* W1 = (const float*)d_in[1];
    const float* b1 = (const float*)d_in[2];
    const float* w2 = (const float*)d_in[3];
    const float* b2 = (const float*)d_in[4];
    const float* Wc = (const float*)d_in[5];
    const float* bc = (const float*)d_in[6];
    float* out = (float*)d_out;

    cudaFuncSetAttribute(gemm_big, cudaFuncAttributeMaxDynamicSharedMemorySize, SMEM_BYTES);

    k_round_x<<<(BT_ * (D_ / 8)) / 256, 256>>>(x);                 // 16384 blocks
    k_pack_w<<<(NBIG * (D_ / 8)) / 256, 256>>>(W1, Wc);            // 1536 blocks
    k_init_s<<<BT_ / 256, 256>>>(b2);

    dim3 gg(NBIG / BN, BT_ / BM);   // (12, 256)
    gemm_big<<<gg, 256, SMEM_BYTES>>>(b1, w2);

    k_maxexp<<<B_, 256>>>();

    dim3 gp(NTILE, B_);
    k_partial<<<gp, 256>>>();
    k_scan<<<B_, 256>>>();
    k_final<<<gp, 256>>>(bc, out);
}